// round 15
// baseline (speedup 1.0000x reference)
#include <cuda_runtime.h>
#include <cuda_bf16.h>
#include <cstdint>

#define NN 25000
#define EE 400000
#define DD 256
#define FEAT 32
#define HOPS 4
#define NB 98   // scan blocks: ceil(25000/256)

// ---------------- device scratch (static, no allocation) ----------------
__device__ __align__(16) float g_h  [(size_t)NN * DD];
__device__ __align__(16) float g_h2 [(size_t)NN * DD];
__device__ __align__(16) float g_S  [(size_t)NN * DD];
// interleaved split of S: [node][256 words], word 2p=hi(pair p), 2p+1=lo
__device__ __align__(16) uint32_t g_S2[(size_t)NN * 256];
__device__ __align__(16) float g_Wc [(size_t)HOPS * 512 * 256];
__device__ __align__(16) float g_bc [(size_t)HOPS * 256];
// interleaved split weights: [hop][n][768 words], word 2w=hi(k-pair w), 2w+1=lo
__device__ __align__(16) uint32_t g_Bti[(size_t)HOPS * 256 * 768];
__device__ __align__(16) float g_deg[NN];
__device__ __align__(16) float g_pool[DD];
__device__ int g_cnt[NN];
__device__ int g_rowptr[NN + 1];
__device__ int g_pos[NN];
__device__ int g_esrc[EE];
__device__ int g_bsum[NB];
__device__ int g_boff[NB];
__device__ int g_is64;

// ---------------- helpers ----------------
__device__ __forceinline__ int idx_at(const void* buf, int is64, size_t idx) {
    if (is64) return (int)((const long long*)buf)[idx];
    return ((const int*)buf)[idx];
}
__device__ __forceinline__ void mma_bf16(float* c, const uint32_t* a, const uint32_t* b) {
    asm volatile(
        "mma.sync.aligned.m16n8k16.row.col.f32.bf16.bf16.f32 "
        "{%0,%1,%2,%3}, {%4,%5,%6,%7}, {%8,%9}, {%0,%1,%2,%3};"
        : "+f"(c[0]), "+f"(c[1]), "+f"(c[2]), "+f"(c[3])
        : "r"(a[0]), "r"(a[1]), "r"(a[2]), "r"(a[3]), "r"(b[0]), "r"(b[1]));
}
__device__ __forceinline__ uint32_t bf16pack(float a, float b) {
    __nv_bfloat162 h;
    h.x = __float2bfloat16_rn(a);
    h.y = __float2bfloat16_rn(b);
    return *reinterpret_cast<uint32_t*>(&h);
}
__device__ __forceinline__ void split_pair(float a, float b, uint32_t& hi, uint32_t& lo) {
    __nv_bfloat16 ha = __float2bfloat16_rn(a);
    __nv_bfloat16 hb = __float2bfloat16_rn(b);
    __nv_bfloat162 hh; hh.x = ha; hh.y = hb;
    hi = *reinterpret_cast<uint32_t*>(&hh);
    lo = bf16pack(a - __bfloat162float(ha), b - __bfloat162float(hb));
}

// ---------------- dtype sniffer ----------------
__global__ void detect_kernel(const int* __restrict__ edges_w, int* __restrict__ is64) {
    __shared__ int nz;
    if (threadIdx.x == 0) nz = 0;
    __syncthreads();
    int any = 0;
    for (int t = threadIdx.x; t < 4096; t += blockDim.x)
        if (edges_w[2 * t + 1] != 0) any = 1;
    if (any) atomicAdd(&nz, 1);
    __syncthreads();
    if (threadIdx.x == 0) *is64 = (nz == 0) ? 1 : 0;
}

// ---------------- utility ----------------
__global__ void zero_i_kernel(int* __restrict__ p, int n) {
    int i = blockIdx.x * blockDim.x + threadIdx.x;
    if (i < n) p[i] = 0;
}
__global__ void zero_f_kernel(float* __restrict__ p, int n) {
    int i = blockIdx.x * blockDim.x + threadIdx.x;
    if (i < n) p[i] = 0.0f;
}

// ---------------- CSR build (parallel scan) ----------------
__global__ void count_kernel(const void* __restrict__ edges, const int* __restrict__ is64p,
                             int* __restrict__ cnt) {
    int e = blockIdx.x * blockDim.x + threadIdx.x;
    if (e >= EE) return;
    int d = idx_at(edges, *is64p, (size_t)EE + e);
    if (d >= 0 && d < NN) atomicAdd(&cnt[d], 1);
}

__global__ void csr_sum_kernel(const int* __restrict__ cnt, int* __restrict__ bsum) {
    int idx = blockIdx.x * 256 + threadIdx.x;
    int v = (idx < NN) ? cnt[idx] : 0;
#pragma unroll
    for (int o = 16; o > 0; o >>= 1) v += __shfl_down_sync(0xFFFFFFFFu, v, o);
    __shared__ int ws[8];
    if ((threadIdx.x & 31) == 0) ws[threadIdx.x >> 5] = v;
    __syncthreads();
    if (threadIdx.x == 0) {
        int s = 0;
#pragma unroll
        for (int i = 0; i < 8; ++i) s += ws[i];
        bsum[blockIdx.x] = s;
    }
}

__global__ void csr_scanb_kernel(const int* __restrict__ bsum, int* __restrict__ boff,
                                 int* __restrict__ rowptr) {
    int t = threadIdx.x, lane = t & 31, w = t >> 5;
    int v = (t < NB) ? bsum[t] : 0;
    int inc = v;
#pragma unroll
    for (int o = 1; o < 32; o <<= 1) {
        int u = __shfl_up_sync(0xFFFFFFFFu, inc, o);
        if (lane >= o) inc += u;
    }
    __shared__ int ws[4];
    if (lane == 31) ws[w] = inc;
    __syncthreads();
    int add = 0;
    for (int i = 0; i < w; ++i) add += ws[i];
    inc += add;
    if (t < NB) boff[t] = inc - v;
    if (t == NB - 1) rowptr[NN] = inc;
}

__global__ void csr_apply_kernel(const int* __restrict__ cnt, const int* __restrict__ boff,
                                 int* __restrict__ rowptr, int* __restrict__ pos,
                                 float* __restrict__ deg) {
    int t = threadIdx.x, lane = t & 31, w = t >> 5;
    int idx = blockIdx.x * 256 + t;
    int c = (idx < NN) ? cnt[idx] : 0;
    int inc = c;
#pragma unroll
    for (int o = 1; o < 32; o <<= 1) {
        int u = __shfl_up_sync(0xFFFFFFFFu, inc, o);
        if (lane >= o) inc += u;
    }
    __shared__ int ws[8];
    if (lane == 31) ws[w] = inc;
    __syncthreads();
    int add = boff[blockIdx.x];
    for (int i = 0; i < w; ++i) add += ws[i];
    int exc = inc - c + add;
    if (idx < NN) {
        rowptr[idx] = exc;
        pos[idx] = exc;
        deg[idx] = (float)c;
    }
}

__global__ void fill_kernel(const void* __restrict__ edges, const int* __restrict__ is64p,
                            int* __restrict__ pos, int* __restrict__ esrc) {
    int e = blockIdx.x * blockDim.x + threadIdx.x;
    if (e >= EE) return;
    int is64 = *is64p;
    int s = idx_at(edges, is64, (size_t)e);
    int d = idx_at(edges, is64, (size_t)EE + e);
    if (d < 0 || d >= NN) return;
    if (s < 0) s = 0; if (s >= NN) s = NN - 1;
    int slot = atomicAdd(&pos[d], 1);
    if (slot >= 0 && slot < EE) esrc[slot] = s;
}

// ---------------- weight composition ----------------
__global__ void compose_kernel(const float* __restrict__ Wm, const float* __restrict__ Wu,
                               float* __restrict__ Wc) {
    int i = blockIdx.x >> 7;
    int k4 = (blockIdx.x & 127) * 4;
    int c = threadIdx.x;
    __shared__ float row[4][256];
#pragma unroll
    for (int q = 0; q < 4; ++q)
        row[q][c] = Wm[((size_t)i * 512 + k4 + q) * 256 + c];
    __syncthreads();
    const float* wub = Wu + ((size_t)i * 512 + 256) * 256;
    float acc0 = 0.f, acc1 = 0.f, acc2 = 0.f, acc3 = 0.f;
#pragma unroll 8
    for (int j = 0; j < 256; ++j) {
        float wv = wub[(size_t)j * 256 + c];
        acc0 += row[0][j] * wv;
        acc1 += row[1][j] * wv;
        acc2 += row[2][j] * wv;
        acc3 += row[3][j] * wv;
    }
    Wc[((size_t)i * 512 + k4 + 0) * 256 + c] = acc0;
    Wc[((size_t)i * 512 + k4 + 1) * 256 + c] = acc1;
    Wc[((size_t)i * 512 + k4 + 2) * 256 + c] = acc2;
    Wc[((size_t)i * 512 + k4 + 3) * 256 + c] = acc3;
}

__global__ void compose_bias_kernel(const float* __restrict__ b_msg,
                                    const float* __restrict__ Wu,
                                    float* __restrict__ bc) {
    int i = blockIdx.x;
    int c = threadIdx.x;
    __shared__ float bm[256];
    bm[c] = b_msg[(size_t)i * 256 + c];
    __syncthreads();
    const float* wub = Wu + ((size_t)i * 512 + 256) * 256;
    float acc = 0.f;
#pragma unroll 8
    for (int j = 0; j < 256; ++j)
        acc += bm[j] * wub[(size_t)j * 256 + c];
    bc[(size_t)i * 256 + c] = acc;
}

// ---------------- B split+transpose, hi/lo interleaved ----------------
__global__ void bsplit_kernel(const float* __restrict__ Wu, const float* __restrict__ Wc,
                              uint32_t* __restrict__ Bti) {
    int hop = blockIdx.x >> 8;
    int n = blockIdx.x & 255;
    const float* wu = Wu + (size_t)hop * 512 * 256;
    const float* wc = Wc + (size_t)hop * 512 * 256;
    size_t base = ((size_t)hop * 256 + n) * 768;
    for (int w = threadIdx.x; w < 384; w += 128) {
        int k = 2 * w;
        float f0 = (k < 256) ? wu[(size_t)k * 256 + n] : wc[(size_t)(k - 256) * 256 + n];
        float f1 = (k + 1 < 256) ? wu[(size_t)(k + 1) * 256 + n]
                                 : wc[(size_t)(k + 1 - 256) * 256 + n];
        uint32_t hi, lo;
        split_pair(f0, f1, hi, lo);
        Bti[base + 2 * w]     = hi;
        Bti[base + 2 * w + 1] = lo;
    }
}

// ---------------- initial node states (8 nodes/block, W_proj in smem) ----------------
__global__ __launch_bounds__(256)
void init_kernel(const float* __restrict__ nodes,
                 const void* __restrict__ types, const int* __restrict__ is64p,
                 const float* __restrict__ type_emb,
                 const float* __restrict__ W_proj,
                 const float* __restrict__ b_proj,
                 float* __restrict__ h) {
    __shared__ float Wp[FEAT * DD];
    __shared__ float sn[8][FEAT];
    int j = threadIdx.x;
    int v0 = blockIdx.x * 8;
    for (int i = j; i < FEAT * DD; i += 256)
        Wp[i] = W_proj[i];
    {
        int vv = v0 + (j >> 5);
        int kk = j & 31;
        sn[j >> 5][kk] = (vv < NN) ? nodes[(size_t)vv * FEAT + kk] : 0.f;
    }
    __syncthreads();
    float bp = b_proj[j];
    int is64 = *is64p;
#pragma unroll 1
    for (int q = 0; q < 8; ++q) {
        int v = v0 + q;
        if (v >= NN) break;
        int t = idx_at(types, is64, (size_t)v);
        if (t < 0) t = 0; if (t > 9) t = 9;
        float acc = bp + type_emb[(size_t)t * DD + j];
#pragma unroll 8
        for (int k = 0; k < FEAT; ++k)
            acc += sn[q][k] * Wp[k * DD + j];
        h[(size_t)v * DD + j] = acc;
    }
}

// ---------------- per-dst gather: S plain + S2 interleaved split ----------------
__global__ __launch_bounds__(256)
void agg_gather_kernel(const int* __restrict__ rowptr,
                       const int* __restrict__ esrc,
                       const float* __restrict__ h,
                       float* __restrict__ S, uint32_t* __restrict__ S2) {
    int v = blockIdx.x * 4 + (threadIdx.x >> 6);
    int tx = (threadIdx.x & 63) * 4;
    if (v >= NN) return;
    int beg = rowptr[v];
    int end = rowptr[v + 1];
    float4 acc = make_float4(0.f, 0.f, 0.f, 0.f);
    int i = beg;
    for (; i + 4 <= end; i += 4) {
        int s0 = esrc[i + 0];
        int s1 = esrc[i + 1];
        int s2 = esrc[i + 2];
        int s3 = esrc[i + 3];
        float4 a0 = *reinterpret_cast<const float4*>(h + (size_t)s0 * DD + tx);
        float4 a1 = *reinterpret_cast<const float4*>(h + (size_t)s1 * DD + tx);
        float4 a2 = *reinterpret_cast<const float4*>(h + (size_t)s2 * DD + tx);
        float4 a3 = *reinterpret_cast<const float4*>(h + (size_t)s3 * DD + tx);
        acc.x += (a0.x + a1.x) + (a2.x + a3.x);
        acc.y += (a0.y + a1.y) + (a2.y + a3.y);
        acc.z += (a0.z + a1.z) + (a2.z + a3.z);
        acc.w += (a0.w + a1.w) + (a2.w + a3.w);
    }
    for (; i < end; ++i) {
        float4 a = *reinterpret_cast<const float4*>(h + (size_t)esrc[i] * DD + tx);
        acc.x += a.x; acc.y += a.y; acc.z += a.z; acc.w += a.w;
    }
    *reinterpret_cast<float4*>(S + (size_t)v * DD + tx) = acc;
    uint4 sp;
    split_pair(acc.x, acc.y, sp.x, sp.y);
    split_pair(acc.z, acc.w, sp.z, sp.w);
    *reinterpret_cast<uint4*>(S2 + (size_t)v * 256 + tx) = sp;
}

// ---------------- hybrid fused hop GEMM (round-13 base) ----------------
// h'[r][c] = relu( h@Wu_top + S@Wc1 + deg*(h@Wc2) + b_upd + deg*bc )
// H path (2/3 CTAs): bf16 m16n8k16 HMMA, hi/lo interleaved smem, LDS.64 frags.
// p=1 A tiles come pre-split from S2 (straight uint4 copy, no cvt).
#define SMU_BYTES 40960

__global__ __launch_bounds__(256, 2)
void hybrid_gemm_kernel(const float* __restrict__ h, const float* __restrict__ S,
                        const uint32_t* __restrict__ S2,
                        const uint32_t* __restrict__ Bti,
                        const float* __restrict__ Wu, const float* __restrict__ Wc,
                        const float* __restrict__ b_upd_i, const float* __restrict__ bc_i,
                        const float* __restrict__ deg,
                        float* __restrict__ out) {
    __shared__ __align__(16) uint8_t smu[SMU_BYTES];
    int tid = threadIdx.x;
    int rowBase = blockIdx.y * 128;
    int colBase = blockIdx.x * 128;
    int lin = blockIdx.y * 2 + blockIdx.x;
    bool useH = (lin % 3) < 2;     // ~67% tensor path

    if (useH) {
        uint32_t* AW = (uint32_t*)(smu);           // [128][40] words interleaved
        uint32_t* BW = (uint32_t*)(smu + 20480);   // [128][40] words interleaved

        int wid = tid >> 5, lane = tid & 31;
        int tq = lane >> 2, tr = lane & 3;
        int warp_m = wid & 1, warp_n = wid >> 1;

        float acc[4][4][4];
#pragma unroll
        for (int mt = 0; mt < 4; ++mt)
#pragma unroll
            for (int nt = 0; nt < 4; ++nt)
#pragma unroll
                for (int q = 0; q < 4; ++q) acc[mt][nt][q] = 0.0f;

        int arow = tid >> 1;
        int halfsel = tid & 1;
        int gr = rowBase + arow;
        bool ok = gr < NN;
        float rs = ok ? deg[gr] : 0.f;

        const uint32_t* Bn = Bti + (size_t)(colBase + arow) * 768;
        const uint32_t* Sn = S2 + (size_t)(ok ? gr : 0) * 256;
        uint32_t* aw = AW + arow * 40 + halfsel * 16;
        uint32_t* bw = BW + arow * 40 + halfsel * 16;

#pragma unroll 1
        for (int p = 0; p < 3; ++p) {
            bool scaled = (p == 2);
            const float* X = (p == 2) ? h : ((p == 0) ? h : S);
#pragma unroll 1
            for (int kt = 0; kt < 8; ++kt) {
                int k0 = kt * 32;
                __syncthreads();
                if (p == 1) {
                    // --- A tile from pre-split S2: straight copy ---
                    int sw0 = k0 + halfsel * 16;
                    uint4 z = make_uint4(0, 0, 0, 0);
#pragma unroll
                    for (int i = 0; i < 4; ++i)
                        *reinterpret_cast<uint4*>(aw + 4 * i) =
                            ok ? *reinterpret_cast<const uint4*>(Sn + sw0 + 4 * i) : z;
                } else {
                    // --- A tile: load fp32, split, store interleaved ---
                    float4 v[4];
                    if (ok) {
                        const float4* src = reinterpret_cast<const float4*>(
                            X + (size_t)gr * DD + k0 + halfsel * 16);
#pragma unroll
                        for (int i = 0; i < 4; ++i) v[i] = src[i];
                        if (scaled) {
#pragma unroll
                            for (int i = 0; i < 4; ++i) {
                                v[i].x *= rs; v[i].y *= rs; v[i].z *= rs; v[i].w *= rs;
                            }
                        }
                    } else {
#pragma unroll
                        for (int i = 0; i < 4; ++i) v[i] = make_float4(0.f, 0.f, 0.f, 0.f);
                    }
#pragma unroll
                    for (int i = 0; i < 4; ++i) {
                        uint4 pk;
                        split_pair(v[i].x, v[i].y, pk.x, pk.y);
                        split_pair(v[i].z, v[i].w, pk.z, pk.w);
                        *reinterpret_cast<uint4*>(aw + 4 * i) = pk;
                    }
                }
                // --- B tile: straight uint4 copy of pre-interleaved words ---
                {
                    int bw0 = (p * 8 + kt) * 32 + halfsel * 16;
#pragma unroll
                    for (int i = 0; i < 4; ++i)
                        *reinterpret_cast<uint4*>(bw + 4 * i) =
                            *reinterpret_cast<const uint4*>(Bn + bw0 + 4 * i);
                }
                __syncthreads();
                // --- compute: 2 k16 steps, LDS.64 fragment loads ---
#pragma unroll
                for (int ks = 0; ks < 2; ++ks) {
                    int kw2 = ks * 16 + tr * 2;
                    uint32_t ah[4][4], al[4][4], bh[4][2], bl[4][2];
#pragma unroll
                    for (int mt = 0; mt < 4; ++mt) {
                        int base = (warp_m * 64 + mt * 16 + tq) * 40 + kw2;
                        uint2 q0 = *reinterpret_cast<const uint2*>(AW + base);
                        uint2 q1 = *reinterpret_cast<const uint2*>(AW + base + 8 * 40);
                        uint2 q2 = *reinterpret_cast<const uint2*>(AW + base + 8);
                        uint2 q3 = *reinterpret_cast<const uint2*>(AW + base + 8 * 40 + 8);
                        ah[mt][0] = q0.x; al[mt][0] = q0.y;
                        ah[mt][1] = q1.x; al[mt][1] = q1.y;
                        ah[mt][2] = q2.x; al[mt][2] = q2.y;
                        ah[mt][3] = q3.x; al[mt][3] = q3.y;
                    }
#pragma unroll
                    for (int nt = 0; nt < 4; ++nt) {
                        int base = (warp_n * 32 + nt * 8 + tq) * 40 + kw2;
                        uint2 r0 = *reinterpret_cast<const uint2*>(BW + base);
                        uint2 r1 = *reinterpret_cast<const uint2*>(BW + base + 8);
                        bh[nt][0] = r0.x; bl[nt][0] = r0.y;
                        bh[nt][1] = r1.x; bl[nt][1] = r1.y;
                    }
#pragma unroll
                    for (int mt = 0; mt < 4; ++mt)
#pragma unroll
                        for (int nt = 0; nt < 4; ++nt) {
                            mma_bf16(acc[mt][nt], ah[mt], bl[nt]);
                            mma_bf16(acc[mt][nt], al[mt], bh[nt]);
                            mma_bf16(acc[mt][nt], ah[mt], bh[nt]);
                        }
                }
            }
        }
        // epilogue
#pragma unroll
        for (int mt = 0; mt < 4; ++mt) {
            int r0 = rowBase + warp_m * 64 + mt * 16 + tq;
            int r1 = r0 + 8;
            float d0 = (r0 < NN) ? deg[r0] : 0.f;
            float d1 = (r1 < NN) ? deg[r1] : 0.f;
#pragma unroll
            for (int nt = 0; nt < 4; ++nt) {
                int c = colBase + warp_n * 32 + nt * 8 + tr * 2;
                float bu0 = b_upd_i[c], bu1 = b_upd_i[c + 1];
                float bb0 = bc_i[c],   bb1 = bc_i[c + 1];
                if (r0 < NN) {
                    float2 v;
                    v.x = fmaxf(acc[mt][nt][0] + bu0 + d0 * bb0, 0.f);
                    v.y = fmaxf(acc[mt][nt][1] + bu1 + d0 * bb1, 0.f);
                    *reinterpret_cast<float2*>(out + (size_t)r0 * DD + c) = v;
                }
                if (r1 < NN) {
                    float2 v;
                    v.x = fmaxf(acc[mt][nt][2] + bu0 + d1 * bb0, 0.f);
                    v.y = fmaxf(acc[mt][nt][3] + bu1 + d1 * bb1, 0.f);
                    *reinterpret_cast<float2*>(out + (size_t)r1 * DD + c) = v;
                }
            }
        }
    } else {
        // ======== fp32 FFMA path (BKK=32) ========
        float* Af = (float*)smu;             // [32][128]
        float* Bf = (float*)(smu + 16384);   // [32][128]
        int tx = tid & 15, ty = tid >> 4;

        const float* Xs[3] = { h, S, h };
        const float* Bp[3] = { Wu, Wc, Wc + 65536 };

        float acc[8][8];
#pragma unroll
        for (int i = 0; i < 8; ++i)
#pragma unroll
            for (int j = 0; j < 8; ++j) acc[i][j] = 0.0f;

        int la_row = tid >> 1, la_k = (tid & 1) * 16;
        int lb_k = tid >> 3, lb_col = (tid & 7) * 16;
        int gr = rowBase + la_row;
        bool ok = gr < NN;
        float rs = ok ? deg[gr] : 0.f;

#pragma unroll 1
        for (int p = 0; p < 3; ++p) {
            const float* X = Xs[p];
            const float* B = Bp[p];
            bool scaled = (p == 2);
#pragma unroll 1
            for (int k0 = 0; k0 < DD; k0 += 32) {
                float4 av[4];
#pragma unroll
                for (int i = 0; i < 4; ++i) av[i] = make_float4(0.f, 0.f, 0.f, 0.f);
                if (ok) {
                    const float4* src = reinterpret_cast<const float4*>(
                        X + (size_t)gr * DD + k0 + la_k);
#pragma unroll
                    for (int i = 0; i < 4; ++i) av[i] = src[i];
                    if (scaled) {
#pragma unroll
                        for (int i = 0; i < 4; ++i) {
                            av[i].x *= rs; av[i].y *= rs; av[i].z *= rs; av[i].w *= rs;
                        }
                    }
                }
                const float4* bsrc = reinterpret_cast<const float4*>(
                    B + (size_t)(k0 + lb_k) * DD + colBase + lb_col);
                float4 bv[4];
#pragma unroll
                for (int i = 0; i < 4; ++i) bv[i] = bsrc[i];
#pragma unroll
                for (int i = 0; i < 4; ++i) {
                    Af[(la_k + 4 * i + 0) * 128 + la_row] = av[i].x;
                    Af[(la_k + 4 * i + 1) * 128 + la_row] = av[i].y;
                    Af[(la_k + 4 * i + 2) * 128 + la_row] = av[i].z;
                    Af[(la_k + 4 * i + 3) * 128 + la_row] = av[i].w;
                    *reinterpret_cast<float4*>(&Bf[lb_k * 128 + lb_col + 4 * i]) = bv[i];
                }
                __syncthreads();
#pragma unroll
                for (int k = 0; k < 32; ++k) {
                    float a[8], b[8];
                    *reinterpret_cast<float4*>(&a[0]) =
                        *reinterpret_cast<const float4*>(&Af[k * 128 + ty * 4]);
                    *reinterpret_cast<float4*>(&a[4]) =
                        *reinterpret_cast<const float4*>(&Af[k * 128 + 64 + ty * 4]);
                    *reinterpret_cast<float4*>(&b[0]) =
                        *reinterpret_cast<const float4*>(&Bf[k * 128 + tx * 4]);
                    *reinterpret_cast<float4*>(&b[4]) =
                        *reinterpret_cast<const float4*>(&Bf[k * 128 + 64 + tx * 4]);
#pragma unroll
                    for (int i = 0; i < 8; ++i)
#pragma unroll
                        for (int j = 0; j < 8; ++j)
                            acc[i][j] += a[i] * b[j];
                }
                __syncthreads();
            }
        }
#pragma unroll
        for (int i = 0; i < 8; ++i) {
            int rloc = (i < 4) ? (ty * 4 + i) : (64 + ty * 4 + i - 4);
            int r = rowBase + rloc;
            if (r >= NN) continue;
            float dr = deg[r];
#pragma unroll
            for (int g = 0; g < 2; ++g) {
                int c0 = colBase + g * 64 + tx * 4;
                float4 v;
                float* vp = &v.x;
#pragma unroll
                for (int j = 0; j < 4; ++j) {
                    int jj = g * 4 + j;
                    vp[j] = fmaxf(acc[i][jj] + b_upd_i[c0 + j] + dr * bc_i[c0 + j], 0.f);
                }
                *reinterpret_cast<float4*>(out + (size_t)r * DD + c0) = v;
            }
        }
    }
}

// ---------------- max pool over nodes ----------------
__global__ void pool_kernel(const float* __restrict__ h, float* __restrict__ pool) {
    int j = threadIdx.x;
    int r0 = blockIdx.x * 256;
    int r1 = min(r0 + 256, NN);
    float m = 0.0f;
    for (int r = r0; r < r1; ++r)
        m = fmaxf(m, h[(size_t)r * DD + j]);
    atomicMax(reinterpret_cast<int*>(&pool[j]), __float_as_int(m));
}

// ---------------- final projection ----------------
__global__ void out_kernel(const float* __restrict__ pool,
                           const float* __restrict__ W_out,
                           const float* __restrict__ b_out,
                           float* __restrict__ out) {
    __shared__ float sp[DD];
    int j = threadIdx.x;
    sp[j] = pool[j];
    __syncthreads();
    float acc = b_out[j];
#pragma unroll 8
    for (int k = 0; k < DD; ++k)
        acc += sp[k] * W_out[(size_t)k * DD + j];
    out[j] = acc;
}

// ---------------- launch ----------------
extern "C" void kernel_launch(void* const* d_in, const int* in_sizes, int n_in,
                              void* d_out, int out_size) {
    const float* nodes      = (const float*)d_in[0];
    const void*  edges      = d_in[1];
    const void*  node_types = d_in[2];
    const float* type_emb   = (const float*)d_in[3];
    const float* W_proj     = (const float*)d_in[4];
    const float* b_proj     = (const float*)d_in[5];
    const float* W_msg      = (const float*)d_in[6];
    const float* b_msg      = (const float*)d_in[7];
    const float* W_upd      = (const float*)d_in[8];
    const float* b_upd      = (const float*)d_in[9];
    const float* W_out      = (const float*)d_in[10];
    const float* b_out      = (const float*)d_in[11];
    float* out = (float*)d_out;

    float *h_p, *h2_p, *S_p, *Wc_p, *bc_p, *deg_p, *pool_p;
    uint32_t *Bti_p, *S2_p;
    int *cnt_p, *rowptr_p, *pos_p, *esrc_p, *is64_p, *bsum_p, *boff_p;
    cudaGetSymbolAddress((void**)&h_p,      g_h);
    cudaGetSymbolAddress((void**)&h2_p,     g_h2);
    cudaGetSymbolAddress((void**)&S_p,      g_S);
    cudaGetSymbolAddress((void**)&S2_p,     g_S2);
    cudaGetSymbolAddress((void**)&Wc_p,     g_Wc);
    cudaGetSymbolAddress((void**)&bc_p,     g_bc);
    cudaGetSymbolAddress((void**)&Bti_p,    g_Bti);
    cudaGetSymbolAddress((void**)&deg_p,    g_deg);
    cudaGetSymbolAddress((void**)&pool_p,   g_pool);
    cudaGetSymbolAddress((void**)&cnt_p,    g_cnt);
    cudaGetSymbolAddress((void**)&rowptr_p, g_rowptr);
    cudaGetSymbolAddress((void**)&pos_p,    g_pos);
    cudaGetSymbolAddress((void**)&esrc_p,   g_esrc);
    cudaGetSymbolAddress((void**)&is64_p,   g_is64);
    cudaGetSymbolAddress((void**)&bsum_p,   g_bsum);
    cudaGetSymbolAddress((void**)&boff_p,   g_boff);

    // sniff index dtype
    detect_kernel<<<1, 256>>>((const int*)edges, is64_p);

    // CSR build (parallel scan)
    zero_i_kernel<<<(NN + 255) / 256, 256>>>(cnt_p, NN);
    count_kernel<<<(EE + 255) / 256, 256>>>(edges, is64_p, cnt_p);
    csr_sum_kernel<<<NB, 256>>>(cnt_p, bsum_p);
    csr_scanb_kernel<<<1, 128>>>(bsum_p, boff_p, rowptr_p);
    csr_apply_kernel<<<NB, 256>>>(cnt_p, boff_p, rowptr_p, pos_p, deg_p);
    fill_kernel<<<(EE + 255) / 256, 256>>>(edges, is64_p, pos_p, esrc_p);

    // composed weights + bias + interleaved split B
    compose_kernel<<<HOPS * 128, 256>>>(W_msg, W_upd, Wc_p);
    compose_bias_kernel<<<HOPS, 256>>>(b_msg, W_upd, bc_p);
    bsplit_kernel<<<HOPS * 256, 128>>>(W_upd, Wc_p, Bti_p);

    // initial states
    init_kernel<<<(NN + 7) / 8, 256>>>(nodes, node_types, is64_p, type_emb,
                                       W_proj, b_proj, h_p);

    float* h_cur = h_p;
    float* h_nxt = h2_p;
    dim3 ggrid(2, (NN + 127) / 128);

    for (int i = 0; i < HOPS; ++i) {
        agg_gather_kernel<<<(NN + 3) / 4, 256>>>(rowptr_p, esrc_p, h_cur, S_p, S2_p);
        hybrid_gemm_kernel<<<ggrid, 256>>>(
            h_cur, S_p, S2_p,
            Bti_p + (size_t)i * 256 * 768,
            W_upd + (size_t)i * 512 * 256, Wc_p + (size_t)i * 512 * 256,
            b_upd + (size_t)i * DD, bc_p + (size_t)i * DD,
            deg_p, h_nxt);
        float* t = h_cur; h_cur = h_nxt; h_nxt = t;
    }

    // pool + output
    zero_f_kernel<<<1, DD>>>(pool_p, DD);
    pool_kernel<<<(NN + 255) / 256, DD>>>(h_cur, pool_p);
    out_kernel<<<1, DD>>>(pool_p, W_out, b_out, out);
}

// round 16
// speedup vs baseline: 1.0749x; 1.0749x over previous
#include <cuda_runtime.h>
#include <cuda_bf16.h>
#include <cstdint>

#define NN 25000
#define EE 400000
#define DD 256
#define FEAT 32
#define HOPS 4
#define NB 98   // scan blocks: ceil(25000/256)

// ---------------- device scratch (static, no allocation) ----------------
__device__ __align__(16) float g_h  [(size_t)NN * DD];
__device__ __align__(16) float g_h2 [(size_t)NN * DD];
__device__ __align__(16) float g_S  [(size_t)NN * DD];
__device__ __align__(16) float g_Wc [(size_t)HOPS * 512 * 256];
__device__ __align__(16) float g_bc [(size_t)HOPS * 256];
// interleaved split weights: [hop][n][768 words], word 2w=hi(k-pair w), 2w+1=lo
__device__ __align__(16) uint32_t g_Bti[(size_t)HOPS * 256 * 768];
__device__ __align__(16) float g_deg[NN];
__device__ __align__(16) float g_pool[DD];
__device__ int g_cnt[NN];
__device__ int g_rowptr[NN + 1];
__device__ int g_pos[NN];
__device__ int g_esrc[EE];
__device__ int g_bsum[NB];
__device__ int g_boff[NB];
__device__ int g_is64;

// ---------------- helpers ----------------
__device__ __forceinline__ int idx_at(const void* buf, int is64, size_t idx) {
    if (is64) return (int)((const long long*)buf)[idx];
    return ((const int*)buf)[idx];
}
__device__ __forceinline__ void mma_bf16(float* c, const uint32_t* a, const uint32_t* b) {
    asm volatile(
        "mma.sync.aligned.m16n8k16.row.col.f32.bf16.bf16.f32 "
        "{%0,%1,%2,%3}, {%4,%5,%6,%7}, {%8,%9}, {%0,%1,%2,%3};"
        : "+f"(c[0]), "+f"(c[1]), "+f"(c[2]), "+f"(c[3])
        : "r"(a[0]), "r"(a[1]), "r"(a[2]), "r"(a[3]), "r"(b[0]), "r"(b[1]));
}
__device__ __forceinline__ uint32_t bf16pack(float a, float b) {
    __nv_bfloat162 h;
    h.x = __float2bfloat16_rn(a);
    h.y = __float2bfloat16_rn(b);
    return *reinterpret_cast<uint32_t*>(&h);
}
__device__ __forceinline__ void split_pair(float a, float b, uint32_t& hi, uint32_t& lo) {
    __nv_bfloat16 ha = __float2bfloat16_rn(a);
    __nv_bfloat16 hb = __float2bfloat16_rn(b);
    __nv_bfloat162 hh; hh.x = ha; hh.y = hb;
    hi = *reinterpret_cast<uint32_t*>(&hh);
    lo = bf16pack(a - __bfloat162float(ha), b - __bfloat162float(hb));
}

// ---------------- dtype sniffer ----------------
__global__ void detect_kernel(const int* __restrict__ edges_w, int* __restrict__ is64) {
    __shared__ int nz;
    if (threadIdx.x == 0) nz = 0;
    __syncthreads();
    int any = 0;
    for (int t = threadIdx.x; t < 4096; t += blockDim.x)
        if (edges_w[2 * t + 1] != 0) any = 1;
    if (any) atomicAdd(&nz, 1);
    __syncthreads();
    if (threadIdx.x == 0) *is64 = (nz == 0) ? 1 : 0;
}

// ---------------- utility ----------------
__global__ void zero_i_kernel(int* __restrict__ p, int n) {
    int i = blockIdx.x * blockDim.x + threadIdx.x;
    if (i < n) p[i] = 0;
}
__global__ void zero_f_kernel(float* __restrict__ p, int n) {
    int i = blockIdx.x * blockDim.x + threadIdx.x;
    if (i < n) p[i] = 0.0f;
}

// ---------------- CSR build (parallel scan) ----------------
__global__ void count_kernel(const void* __restrict__ edges, const int* __restrict__ is64p,
                             int* __restrict__ cnt) {
    int e = blockIdx.x * blockDim.x + threadIdx.x;
    if (e >= EE) return;
    int d = idx_at(edges, *is64p, (size_t)EE + e);
    if (d >= 0 && d < NN) atomicAdd(&cnt[d], 1);
}

__global__ void csr_sum_kernel(const int* __restrict__ cnt, int* __restrict__ bsum) {
    int idx = blockIdx.x * 256 + threadIdx.x;
    int v = (idx < NN) ? cnt[idx] : 0;
#pragma unroll
    for (int o = 16; o > 0; o >>= 1) v += __shfl_down_sync(0xFFFFFFFFu, v, o);
    __shared__ int ws[8];
    if ((threadIdx.x & 31) == 0) ws[threadIdx.x >> 5] = v;
    __syncthreads();
    if (threadIdx.x == 0) {
        int s = 0;
#pragma unroll
        for (int i = 0; i < 8; ++i) s += ws[i];
        bsum[blockIdx.x] = s;
    }
}

__global__ void csr_scanb_kernel(const int* __restrict__ bsum, int* __restrict__ boff,
                                 int* __restrict__ rowptr) {
    int t = threadIdx.x, lane = t & 31, w = t >> 5;
    int v = (t < NB) ? bsum[t] : 0;
    int inc = v;
#pragma unroll
    for (int o = 1; o < 32; o <<= 1) {
        int u = __shfl_up_sync(0xFFFFFFFFu, inc, o);
        if (lane >= o) inc += u;
    }
    __shared__ int ws[4];
    if (lane == 31) ws[w] = inc;
    __syncthreads();
    int add = 0;
    for (int i = 0; i < w; ++i) add += ws[i];
    inc += add;
    if (t < NB) boff[t] = inc - v;
    if (t == NB - 1) rowptr[NN] = inc;
}

__global__ void csr_apply_kernel(const int* __restrict__ cnt, const int* __restrict__ boff,
                                 int* __restrict__ rowptr, int* __restrict__ pos,
                                 float* __restrict__ deg) {
    int t = threadIdx.x, lane = t & 31, w = t >> 5;
    int idx = blockIdx.x * 256 + t;
    int c = (idx < NN) ? cnt[idx] : 0;
    int inc = c;
#pragma unroll
    for (int o = 1; o < 32; o <<= 1) {
        int u = __shfl_up_sync(0xFFFFFFFFu, inc, o);
        if (lane >= o) inc += u;
    }
    __shared__ int ws[8];
    if (lane == 31) ws[w] = inc;
    __syncthreads();
    int add = boff[blockIdx.x];
    for (int i = 0; i < w; ++i) add += ws[i];
    int exc = inc - c + add;
    if (idx < NN) {
        rowptr[idx] = exc;
        pos[idx] = exc;
        deg[idx] = (float)c;
    }
}

__global__ void fill_kernel(const void* __restrict__ edges, const int* __restrict__ is64p,
                            int* __restrict__ pos, int* __restrict__ esrc) {
    int e = blockIdx.x * blockDim.x + threadIdx.x;
    if (e >= EE) return;
    int is64 = *is64p;
    int s = idx_at(edges, is64, (size_t)e);
    int d = idx_at(edges, is64, (size_t)EE + e);
    if (d < 0 || d >= NN) return;
    if (s < 0) s = 0; if (s >= NN) s = NN - 1;
    int slot = atomicAdd(&pos[d], 1);
    if (slot >= 0 && slot < EE) esrc[slot] = s;
}

// ---------------- weight composition ----------------
__global__ void compose_kernel(const float* __restrict__ Wm, const float* __restrict__ Wu,
                               float* __restrict__ Wc) {
    int i = blockIdx.x >> 7;
    int k4 = (blockIdx.x & 127) * 4;
    int c = threadIdx.x;
    __shared__ float row[4][256];
#pragma unroll
    for (int q = 0; q < 4; ++q)
        row[q][c] = Wm[((size_t)i * 512 + k4 + q) * 256 + c];
    __syncthreads();
    const float* wub = Wu + ((size_t)i * 512 + 256) * 256;
    float acc0 = 0.f, acc1 = 0.f, acc2 = 0.f, acc3 = 0.f;
#pragma unroll 8
    for (int j = 0; j < 256; ++j) {
        float wv = wub[(size_t)j * 256 + c];
        acc0 += row[0][j] * wv;
        acc1 += row[1][j] * wv;
        acc2 += row[2][j] * wv;
        acc3 += row[3][j] * wv;
    }
    Wc[((size_t)i * 512 + k4 + 0) * 256 + c] = acc0;
    Wc[((size_t)i * 512 + k4 + 1) * 256 + c] = acc1;
    Wc[((size_t)i * 512 + k4 + 2) * 256 + c] = acc2;
    Wc[((size_t)i * 512 + k4 + 3) * 256 + c] = acc3;
}

__global__ void compose_bias_kernel(const float* __restrict__ b_msg,
                                    const float* __restrict__ Wu,
                                    float* __restrict__ bc) {
    int i = blockIdx.x;
    int c = threadIdx.x;
    __shared__ float bm[256];
    bm[c] = b_msg[(size_t)i * 256 + c];
    __syncthreads();
    const float* wub = Wu + ((size_t)i * 512 + 256) * 256;
    float acc = 0.f;
#pragma unroll 8
    for (int j = 0; j < 256; ++j)
        acc += bm[j] * wub[(size_t)j * 256 + c];
    bc[(size_t)i * 256 + c] = acc;
}

// ---------------- B split+transpose, hi/lo interleaved ----------------
__global__ void bsplit_kernel(const float* __restrict__ Wu, const float* __restrict__ Wc,
                              uint32_t* __restrict__ Bti) {
    int hop = blockIdx.x >> 8;
    int n = blockIdx.x & 255;
    const float* wu = Wu + (size_t)hop * 512 * 256;
    const float* wc = Wc + (size_t)hop * 512 * 256;
    size_t base = ((size_t)hop * 256 + n) * 768;
    for (int w = threadIdx.x; w < 384; w += 128) {
        int k = 2 * w;
        float f0 = (k < 256) ? wu[(size_t)k * 256 + n] : wc[(size_t)(k - 256) * 256 + n];
        float f1 = (k + 1 < 256) ? wu[(size_t)(k + 1) * 256 + n]
                                 : wc[(size_t)(k + 1 - 256) * 256 + n];
        uint32_t hi, lo;
        split_pair(f0, f1, hi, lo);
        Bti[base + 2 * w]     = hi;
        Bti[base + 2 * w + 1] = lo;
    }
}

// ---------------- initial node states (8 nodes/block, W_proj in smem) ----------------
__global__ __launch_bounds__(256)
void init_kernel(const float* __restrict__ nodes,
                 const void* __restrict__ types, const int* __restrict__ is64p,
                 const float* __restrict__ type_emb,
                 const float* __restrict__ W_proj,
                 const float* __restrict__ b_proj,
                 float* __restrict__ h) {
    __shared__ float Wp[FEAT * DD];
    __shared__ float sn[8][FEAT];
    int j = threadIdx.x;
    int v0 = blockIdx.x * 8;
    for (int i = j; i < FEAT * DD; i += 256)
        Wp[i] = W_proj[i];
    {
        int vv = v0 + (j >> 5);
        int kk = j & 31;
        sn[j >> 5][kk] = (vv < NN) ? nodes[(size_t)vv * FEAT + kk] : 0.f;
    }
    __syncthreads();
    float bp = b_proj[j];
    int is64 = *is64p;
#pragma unroll 1
    for (int q = 0; q < 8; ++q) {
        int v = v0 + q;
        if (v >= NN) break;
        int t = idx_at(types, is64, (size_t)v);
        if (t < 0) t = 0; if (t > 9) t = 9;
        float acc = bp + type_emb[(size_t)t * DD + j];
#pragma unroll 8
        for (int k = 0; k < FEAT; ++k)
            acc += sn[q][k] * Wp[k * DD + j];
        h[(size_t)v * DD + j] = acc;
    }
}

// ---------------- per-dst gather (float4, 4 nodes/block, 8-deep MLP) ----------------
__global__ __launch_bounds__(256)
void agg_gather_kernel(const int* __restrict__ rowptr,
                       const int* __restrict__ esrc,
                       const float* __restrict__ h,
                       float* __restrict__ S) {
    int v = blockIdx.x * 4 + (threadIdx.x >> 6);
    int tx = (threadIdx.x & 63) * 4;
    if (v >= NN) return;
    int beg = rowptr[v];
    int end = rowptr[v + 1];
    float4 acc = make_float4(0.f, 0.f, 0.f, 0.f);
    int i = beg;
    for (; i + 8 <= end; i += 8) {
        int s0 = esrc[i + 0];
        int s1 = esrc[i + 1];
        int s2 = esrc[i + 2];
        int s3 = esrc[i + 3];
        int s4 = esrc[i + 4];
        int s5 = esrc[i + 5];
        int s6 = esrc[i + 6];
        int s7 = esrc[i + 7];
        float4 a0 = *reinterpret_cast<const float4*>(h + (size_t)s0 * DD + tx);
        float4 a1 = *reinterpret_cast<const float4*>(h + (size_t)s1 * DD + tx);
        float4 a2 = *reinterpret_cast<const float4*>(h + (size_t)s2 * DD + tx);
        float4 a3 = *reinterpret_cast<const float4*>(h + (size_t)s3 * DD + tx);
        float4 a4 = *reinterpret_cast<const float4*>(h + (size_t)s4 * DD + tx);
        float4 a5 = *reinterpret_cast<const float4*>(h + (size_t)s5 * DD + tx);
        float4 a6 = *reinterpret_cast<const float4*>(h + (size_t)s6 * DD + tx);
        float4 a7 = *reinterpret_cast<const float4*>(h + (size_t)s7 * DD + tx);
        acc.x += ((a0.x + a1.x) + (a2.x + a3.x)) + ((a4.x + a5.x) + (a6.x + a7.x));
        acc.y += ((a0.y + a1.y) + (a2.y + a3.y)) + ((a4.y + a5.y) + (a6.y + a7.y));
        acc.z += ((a0.z + a1.z) + (a2.z + a3.z)) + ((a4.z + a5.z) + (a6.z + a7.z));
        acc.w += ((a0.w + a1.w) + (a2.w + a3.w)) + ((a4.w + a5.w) + (a6.w + a7.w));
    }
    for (; i < end; ++i) {
        float4 a = *reinterpret_cast<const float4*>(h + (size_t)esrc[i] * DD + tx);
        acc.x += a.x; acc.y += a.y; acc.z += a.z; acc.w += a.w;
    }
    *reinterpret_cast<float4*>(S + (size_t)v * DD + tx) = acc;
}

// ---------------- hybrid fused hop GEMM (round-13 proven) ----------------
// h'[r][c] = relu( h@Wu_top + S@Wc1 + deg*(h@Wc2) + b_upd + deg*bc )
// H path (2/3 CTAs): bf16 m16n8k16 HMMA, hi/lo interleaved smem, LDS.64 frags.
#define SMU_BYTES 40960

__global__ __launch_bounds__(256, 2)
void hybrid_gemm_kernel(const float* __restrict__ h, const float* __restrict__ S,
                        const uint32_t* __restrict__ Bti,
                        const float* __restrict__ Wu, const float* __restrict__ Wc,
                        const float* __restrict__ b_upd_i, const float* __restrict__ bc_i,
                        const float* __restrict__ deg,
                        float* __restrict__ out) {
    __shared__ __align__(16) uint8_t smu[SMU_BYTES];
    int tid = threadIdx.x;
    int rowBase = blockIdx.y * 128;
    int colBase = blockIdx.x * 128;
    int lin = blockIdx.y * 2 + blockIdx.x;
    bool useH = (lin % 3) < 2;     // ~67% tensor path

    const float* Xs[3] = { h, S, h };

    if (useH) {
        uint32_t* AW = (uint32_t*)(smu);           // [128][40] words interleaved
        uint32_t* BW = (uint32_t*)(smu + 20480);   // [128][40] words interleaved

        int wid = tid >> 5, lane = tid & 31;
        int tq = lane >> 2, tr = lane & 3;
        int warp_m = wid & 1, warp_n = wid >> 1;

        float acc[4][4][4];
#pragma unroll
        for (int mt = 0; mt < 4; ++mt)
#pragma unroll
            for (int nt = 0; nt < 4; ++nt)
#pragma unroll
                for (int q = 0; q < 4; ++q) acc[mt][nt][q] = 0.0f;

        int arow = tid >> 1;
        int halfsel = tid & 1;
        int gr = rowBase + arow;
        bool ok = gr < NN;
        float rs = ok ? deg[gr] : 0.f;

        const uint32_t* Bn = Bti + (size_t)(colBase + arow) * 768;
        uint32_t* aw = AW + arow * 40 + halfsel * 16;
        uint32_t* bw = BW + arow * 40 + halfsel * 16;

#pragma unroll 1
        for (int p = 0; p < 3; ++p) {
            const float* X = Xs[p];
            bool scaled = (p == 2);
#pragma unroll 1
            for (int kt = 0; kt < 8; ++kt) {
                int k0 = kt * 32;
                __syncthreads();
                // --- A tile: load 16 floats, split, store interleaved (4x STS.128) ---
                {
                    float4 v[4];
                    if (ok) {
                        const float4* src = reinterpret_cast<const float4*>(
                            X + (size_t)gr * DD + k0 + halfsel * 16);
#pragma unroll
                        for (int i = 0; i < 4; ++i) v[i] = src[i];
                        if (scaled) {
#pragma unroll
                            for (int i = 0; i < 4; ++i) {
                                v[i].x *= rs; v[i].y *= rs; v[i].z *= rs; v[i].w *= rs;
                            }
                        }
                    } else {
#pragma unroll
                        for (int i = 0; i < 4; ++i) v[i] = make_float4(0.f, 0.f, 0.f, 0.f);
                    }
#pragma unroll
                    for (int i = 0; i < 4; ++i) {
                        uint4 pk;
                        split_pair(v[i].x, v[i].y, pk.x, pk.y);
                        split_pair(v[i].z, v[i].w, pk.z, pk.w);
                        *reinterpret_cast<uint4*>(aw + 4 * i) = pk;
                    }
                }
                // --- B tile: straight uint4 copy of pre-interleaved words ---
                {
                    int bw0 = (p * 8 + kt) * 32 + halfsel * 16;
#pragma unroll
                    for (int i = 0; i < 4; ++i)
                        *reinterpret_cast<uint4*>(bw + 4 * i) =
                            *reinterpret_cast<const uint4*>(Bn + bw0 + 4 * i);
                }
                __syncthreads();
                // --- compute: 2 k16 steps, LDS.64 fragment loads ---
#pragma unroll
                for (int ks = 0; ks < 2; ++ks) {
                    int kw2 = ks * 16 + tr * 2;
                    uint32_t ah[4][4], al[4][4], bh[4][2], bl[4][2];
#pragma unroll
                    for (int mt = 0; mt < 4; ++mt) {
                        int base = (warp_m * 64 + mt * 16 + tq) * 40 + kw2;
                        uint2 q0 = *reinterpret_cast<const uint2*>(AW + base);
                        uint2 q1 = *reinterpret_cast<const uint2*>(AW + base + 8 * 40);
                        uint2 q2 = *reinterpret_cast<const uint2*>(AW + base + 8);
                        uint2 q3 = *reinterpret_cast<const uint2*>(AW + base + 8 * 40 + 8);
                        ah[mt][0] = q0.x; al[mt][0] = q0.y;
                        ah[mt][1] = q1.x; al[mt][1] = q1.y;
                        ah[mt][2] = q2.x; al[mt][2] = q2.y;
                        ah[mt][3] = q3.x; al[mt][3] = q3.y;
                    }
#pragma unroll
                    for (int nt = 0; nt < 4; ++nt) {
                        int base = (warp_n * 32 + nt * 8 + tq) * 40 + kw2;
                        uint2 r0 = *reinterpret_cast<const uint2*>(BW + base);
                        uint2 r1 = *reinterpret_cast<const uint2*>(BW + base + 8);
                        bh[nt][0] = r0.x; bl[nt][0] = r0.y;
                        bh[nt][1] = r1.x; bl[nt][1] = r1.y;
                    }
#pragma unroll
                    for (int mt = 0; mt < 4; ++mt)
#pragma unroll
                        for (int nt = 0; nt < 4; ++nt) {
                            mma_bf16(acc[mt][nt], ah[mt], bl[nt]);
                            mma_bf16(acc[mt][nt], al[mt], bh[nt]);
                            mma_bf16(acc[mt][nt], ah[mt], bh[nt]);
                        }
                }
            }
        }
        // epilogue
#pragma unroll
        for (int mt = 0; mt < 4; ++mt) {
            int r0 = rowBase + warp_m * 64 + mt * 16 + tq;
            int r1 = r0 + 8;
            float d0 = (r0 < NN) ? deg[r0] : 0.f;
            float d1 = (r1 < NN) ? deg[r1] : 0.f;
#pragma unroll
            for (int nt = 0; nt < 4; ++nt) {
                int c = colBase + warp_n * 32 + nt * 8 + tr * 2;
                float bu0 = b_upd_i[c], bu1 = b_upd_i[c + 1];
                float bb0 = bc_i[c],   bb1 = bc_i[c + 1];
                if (r0 < NN) {
                    float2 v;
                    v.x = fmaxf(acc[mt][nt][0] + bu0 + d0 * bb0, 0.f);
                    v.y = fmaxf(acc[mt][nt][1] + bu1 + d0 * bb1, 0.f);
                    *reinterpret_cast<float2*>(out + (size_t)r0 * DD + c) = v;
                }
                if (r1 < NN) {
                    float2 v;
                    v.x = fmaxf(acc[mt][nt][2] + bu0 + d1 * bb0, 0.f);
                    v.y = fmaxf(acc[mt][nt][3] + bu1 + d1 * bb1, 0.f);
                    *reinterpret_cast<float2*>(out + (size_t)r1 * DD + c) = v;
                }
            }
        }
    } else {
        // ======== fp32 FFMA path (BKK=16) ========
        float* Af = (float*)smu;            // [16][128]
        float* Bf = (float*)(smu + 8192);   // [16][128]
        int tx = tid & 15, ty = tid >> 4;

        const float* Bp[3] = { Wu, Wc, Wc + 65536 };

        float acc[8][8];
#pragma unroll
        for (int i = 0; i < 8; ++i)
#pragma unroll
            for (int j = 0; j < 8; ++j) acc[i][j] = 0.0f;

        int la_row = tid >> 1, la_k = (tid & 1) * 8;
        int lb_k = tid >> 4, lb_col = (tid & 15) * 8;
        int gr = rowBase + la_row;
        bool ok = gr < NN;
        float rs = ok ? deg[gr] : 0.f;

#pragma unroll 1
        for (int p = 0; p < 3; ++p) {
            const float* X = Xs[p];
            const float* B = Bp[p];
            bool scaled = (p == 2);
#pragma unroll 1
            for (int k0 = 0; k0 < DD; k0 += 16) {
                float4 av0 = make_float4(0.f, 0.f, 0.f, 0.f), av1 = av0;
                if (ok) {
                    const float4* src = reinterpret_cast<const float4*>(
                        X + (size_t)gr * DD + k0 + la_k);
                    av0 = src[0]; av1 = src[1];
                    if (scaled) {
                        av0.x *= rs; av0.y *= rs; av0.z *= rs; av0.w *= rs;
                        av1.x *= rs; av1.y *= rs; av1.z *= rs; av1.w *= rs;
                    }
                }
                const float4* bsrc = reinterpret_cast<const float4*>(
                    B + (size_t)(k0 + lb_k) * DD + colBase + lb_col);
                float4 bv0 = bsrc[0], bv1 = bsrc[1];
                Af[(la_k + 0) * 128 + la_row] = av0.x;
                Af[(la_k + 1) * 128 + la_row] = av0.y;
                Af[(la_k + 2) * 128 + la_row] = av0.z;
                Af[(la_k + 3) * 128 + la_row] = av0.w;
                Af[(la_k + 4) * 128 + la_row] = av1.x;
                Af[(la_k + 5) * 128 + la_row] = av1.y;
                Af[(la_k + 6) * 128 + la_row] = av1.z;
                Af[(la_k + 7) * 128 + la_row] = av1.w;
                *reinterpret_cast<float4*>(&Bf[lb_k * 128 + lb_col]) = bv0;
                *reinterpret_cast<float4*>(&Bf[lb_k * 128 + lb_col + 4]) = bv1;
                __syncthreads();
#pragma unroll
                for (int k = 0; k < 16; ++k) {
                    float a[8], b[8];
                    *reinterpret_cast<float4*>(&a[0]) =
                        *reinterpret_cast<const float4*>(&Af[k * 128 + ty * 4]);
                    *reinterpret_cast<float4*>(&a[4]) =
                        *reinterpret_cast<const float4*>(&Af[k * 128 + 64 + ty * 4]);
                    *reinterpret_cast<float4*>(&b[0]) =
                        *reinterpret_cast<const float4*>(&Bf[k * 128 + tx * 4]);
                    *reinterpret_cast<float4*>(&b[4]) =
                        *reinterpret_cast<const float4*>(&Bf[k * 128 + 64 + tx * 4]);
#pragma unroll
                    for (int i = 0; i < 8; ++i)
#pragma unroll
                        for (int j = 0; j < 8; ++j)
                            acc[i][j] += a[i] * b[j];
                }
                __syncthreads();
            }
        }
#pragma unroll
        for (int i = 0; i < 8; ++i) {
            int rloc = (i < 4) ? (ty * 4 + i) : (64 + ty * 4 + i - 4);
            int r = rowBase + rloc;
            if (r >= NN) continue;
            float dr = deg[r];
#pragma unroll
            for (int g = 0; g < 2; ++g) {
                int c0 = colBase + g * 64 + tx * 4;
                float4 v;
                float* vp = &v.x;
#pragma unroll
                for (int j = 0; j < 4; ++j) {
                    int jj = g * 4 + j;
                    vp[j] = fmaxf(acc[i][jj] + b_upd_i[c0 + j] + dr * bc_i[c0 + j], 0.f);
                }
                *reinterpret_cast<float4*>(out + (size_t)r * DD + c0) = v;
            }
        }
    }
}

// ---------------- max pool over nodes ----------------
__global__ void pool_kernel(const float* __restrict__ h, float* __restrict__ pool) {
    int j = threadIdx.x;
    int r0 = blockIdx.x * 256;
    int r1 = min(r0 + 256, NN);
    float m = 0.0f;
    for (int r = r0; r < r1; ++r)
        m = fmaxf(m, h[(size_t)r * DD + j]);
    atomicMax(reinterpret_cast<int*>(&pool[j]), __float_as_int(m));
}

// ---------------- final projection ----------------
__global__ void out_kernel(const float* __restrict__ pool,
                           const float* __restrict__ W_out,
                           const float* __restrict__ b_out,
                           float* __restrict__ out) {
    __shared__ float sp[DD];
    int j = threadIdx.x;
    sp[j] = pool[j];
    __syncthreads();
    float acc = b_out[j];
#pragma unroll 8
    for (int k = 0; k < DD; ++k)
        acc += sp[k] * W_out[(size_t)k * DD + j];
    out[j] = acc;
}

// ---------------- launch ----------------
extern "C" void kernel_launch(void* const* d_in, const int* in_sizes, int n_in,
                              void* d_out, int out_size) {
    const float* nodes      = (const float*)d_in[0];
    const void*  edges      = d_in[1];
    const void*  node_types = d_in[2];
    const float* type_emb   = (const float*)d_in[3];
    const float* W_proj     = (const float*)d_in[4];
    const float* b_proj     = (const float*)d_in[5];
    const float* W_msg      = (const float*)d_in[6];
    const float* b_msg      = (const float*)d_in[7];
    const float* W_upd      = (const float*)d_in[8];
    const float* b_upd      = (const float*)d_in[9];
    const float* W_out      = (const float*)d_in[10];
    const float* b_out      = (const float*)d_in[11];
    float* out = (float*)d_out;

    float *h_p, *h2_p, *S_p, *Wc_p, *bc_p, *deg_p, *pool_p;
    uint32_t *Bti_p;
    int *cnt_p, *rowptr_p, *pos_p, *esrc_p, *is64_p, *bsum_p, *boff_p;
    cudaGetSymbolAddress((void**)&h_p,      g_h);
    cudaGetSymbolAddress((void**)&h2_p,     g_h2);
    cudaGetSymbolAddress((void**)&S_p,      g_S);
    cudaGetSymbolAddress((void**)&Wc_p,     g_Wc);
    cudaGetSymbolAddress((void**)&bc_p,     g_bc);
    cudaGetSymbolAddress((void**)&Bti_p,    g_Bti);
    cudaGetSymbolAddress((void**)&deg_p,    g_deg);
    cudaGetSymbolAddress((void**)&pool_p,   g_pool);
    cudaGetSymbolAddress((void**)&cnt_p,    g_cnt);
    cudaGetSymbolAddress((void**)&rowptr_p, g_rowptr);
    cudaGetSymbolAddress((void**)&pos_p,    g_pos);
    cudaGetSymbolAddress((void**)&esrc_p,   g_esrc);
    cudaGetSymbolAddress((void**)&is64_p,   g_is64);
    cudaGetSymbolAddress((void**)&bsum_p,   g_bsum);
    cudaGetSymbolAddress((void**)&boff_p,   g_boff);

    // sniff index dtype
    detect_kernel<<<1, 256>>>((const int*)edges, is64_p);

    // CSR build (parallel scan)
    zero_i_kernel<<<(NN + 255) / 256, 256>>>(cnt_p, NN);
    count_kernel<<<(EE + 255) / 256, 256>>>(edges, is64_p, cnt_p);
    csr_sum_kernel<<<NB, 256>>>(cnt_p, bsum_p);
    csr_scanb_kernel<<<1, 128>>>(bsum_p, boff_p, rowptr_p);
    csr_apply_kernel<<<NB, 256>>>(cnt_p, boff_p, rowptr_p, pos_p, deg_p);
    fill_kernel<<<(EE + 255) / 256, 256>>>(edges, is64_p, pos_p, esrc_p);

    // composed weights + bias + interleaved split B
    compose_kernel<<<HOPS * 128, 256>>>(W_msg, W_upd, Wc_p);
    compose_bias_kernel<<<HOPS, 256>>>(b_msg, W_upd, bc_p);
    bsplit_kernel<<<HOPS * 256, 128>>>(W_upd, Wc_p, Bti_p);

    // initial states
    init_kernel<<<(NN + 7) / 8, 256>>>(nodes, node_types, is64_p, type_emb,
                                       W_proj, b_proj, h_p);

    float* h_cur = h_p;
    float* h_nxt = h2_p;
    dim3 ggrid(2, (NN + 127) / 128);

    for (int i = 0; i < HOPS; ++i) {
        agg_gather_kernel<<<(NN + 3) / 4, 256>>>(rowptr_p, esrc_p, h_cur, S_p);
        hybrid_gemm_kernel<<<ggrid, 256>>>(
            h_cur, S_p,
            Bti_p + (size_t)i * 256 * 768,
            W_upd + (size_t)i * 512 * 256, Wc_p + (size_t)i * 512 * 256,
            b_upd + (size_t)i * DD, bc_p + (size_t)i * DD,
            deg_p, h_nxt);
        float* t = h_cur; h_cur = h_nxt; h_nxt = t;
    }

    // pool + output
    zero_f_kernel<<<1, DD>>>(pool_p, DD);
    pool_kernel<<<(NN + 255) / 256, DD>>>(h_cur, pool_p);
    out_kernel<<<1, DD>>>(pool_p, W_out, b_out, out);
}

// round 17
// speedup vs baseline: 1.2943x; 1.2041x over previous
#include <cuda_runtime.h>
#include <cuda_bf16.h>
#include <cstdint>

#define NN 25000
#define EE 400000
#define DD 256
#define FEAT 32
#define HOPS 4
#define NB 98   // scan blocks: ceil(25000/256)

// ---------------- device scratch (static, no allocation) ----------------
__device__ __align__(16) float g_h  [(size_t)NN * DD];
__device__ __align__(16) float g_h2 [(size_t)NN * DD];
__device__ __align__(16) float g_S  [(size_t)NN * DD];
__device__ __align__(16) float g_Wc [(size_t)HOPS * 512 * 256];
__device__ __align__(16) float g_bc [(size_t)HOPS * 256];
// interleaved split weights: [hop][n][768 words], word 2w=hi(k-pair w), 2w+1=lo
__device__ __align__(16) uint32_t g_Bti[(size_t)HOPS * 256 * 768];
__device__ __align__(16) float g_deg[NN];
__device__ __align__(16) float g_pool[DD];
__device__ int g_cnt[NN];
__device__ int g_rowptr[NN + 1];
__device__ int g_pos[NN];
__device__ int g_esrc[EE];
__device__ int g_bsum[NB];
__device__ int g_boff[NB];
__device__ int g_is64;

// ---------------- helpers ----------------
__device__ __forceinline__ int idx_at(const void* buf, int is64, size_t idx) {
    if (is64) return (int)((const long long*)buf)[idx];
    return ((const int*)buf)[idx];
}
__device__ __forceinline__ void mma_bf16(float* c, const uint32_t* a, const uint32_t* b) {
    asm volatile(
        "mma.sync.aligned.m16n8k16.row.col.f32.bf16.bf16.f32 "
        "{%0,%1,%2,%3}, {%4,%5,%6,%7}, {%8,%9}, {%0,%1,%2,%3};"
        : "+f"(c[0]), "+f"(c[1]), "+f"(c[2]), "+f"(c[3])
        : "r"(a[0]), "r"(a[1]), "r"(a[2]), "r"(a[3]), "r"(b[0]), "r"(b[1]));
}
__device__ __forceinline__ uint32_t bf16pack(float a, float b) {
    __nv_bfloat162 h;
    h.x = __float2bfloat16_rn(a);
    h.y = __float2bfloat16_rn(b);
    return *reinterpret_cast<uint32_t*>(&h);
}
__device__ __forceinline__ void split_pair(float a, float b, uint32_t& hi, uint32_t& lo) {
    __nv_bfloat16 ha = __float2bfloat16_rn(a);
    __nv_bfloat16 hb = __float2bfloat16_rn(b);
    __nv_bfloat162 hh; hh.x = ha; hh.y = hb;
    hi = *reinterpret_cast<uint32_t*>(&hh);
    lo = bf16pack(a - __bfloat162float(ha), b - __bfloat162float(hb));
}

// ---------------- dtype sniffer ----------------
__global__ void detect_kernel(const int* __restrict__ edges_w, int* __restrict__ is64) {
    __shared__ int nz;
    if (threadIdx.x == 0) nz = 0;
    __syncthreads();
    int any = 0;
    for (int t = threadIdx.x; t < 4096; t += blockDim.x)
        if (edges_w[2 * t + 1] != 0) any = 1;
    if (any) atomicAdd(&nz, 1);
    __syncthreads();
    if (threadIdx.x == 0) *is64 = (nz == 0) ? 1 : 0;
}

// ---------------- utility ----------------
__global__ void zero_i_kernel(int* __restrict__ p, int n) {
    int i = blockIdx.x * blockDim.x + threadIdx.x;
    if (i < n) p[i] = 0;
}
__global__ void zero_f_kernel(float* __restrict__ p, int n) {
    int i = blockIdx.x * blockDim.x + threadIdx.x;
    if (i < n) p[i] = 0.0f;
}

// ---------------- CSR build (parallel scan) ----------------
__global__ void count_kernel(const void* __restrict__ edges, const int* __restrict__ is64p,
                             int* __restrict__ cnt) {
    int e = blockIdx.x * blockDim.x + threadIdx.x;
    if (e >= EE) return;
    int d = idx_at(edges, *is64p, (size_t)EE + e);
    if (d >= 0 && d < NN) atomicAdd(&cnt[d], 1);
}

__global__ void csr_sum_kernel(const int* __restrict__ cnt, int* __restrict__ bsum) {
    int idx = blockIdx.x * 256 + threadIdx.x;
    int v = (idx < NN) ? cnt[idx] : 0;
#pragma unroll
    for (int o = 16; o > 0; o >>= 1) v += __shfl_down_sync(0xFFFFFFFFu, v, o);
    __shared__ int ws[8];
    if ((threadIdx.x & 31) == 0) ws[threadIdx.x >> 5] = v;
    __syncthreads();
    if (threadIdx.x == 0) {
        int s = 0;
#pragma unroll
        for (int i = 0; i < 8; ++i) s += ws[i];
        bsum[blockIdx.x] = s;
    }
}

__global__ void csr_scanb_kernel(const int* __restrict__ bsum, int* __restrict__ boff,
                                 int* __restrict__ rowptr) {
    int t = threadIdx.x, lane = t & 31, w = t >> 5;
    int v = (t < NB) ? bsum[t] : 0;
    int inc = v;
#pragma unroll
    for (int o = 1; o < 32; o <<= 1) {
        int u = __shfl_up_sync(0xFFFFFFFFu, inc, o);
        if (lane >= o) inc += u;
    }
    __shared__ int ws[4];
    if (lane == 31) ws[w] = inc;
    __syncthreads();
    int add = 0;
    for (int i = 0; i < w; ++i) add += ws[i];
    inc += add;
    if (t < NB) boff[t] = inc - v;
    if (t == NB - 1) rowptr[NN] = inc;
}

__global__ void csr_apply_kernel(const int* __restrict__ cnt, const int* __restrict__ boff,
                                 int* __restrict__ rowptr, int* __restrict__ pos,
                                 float* __restrict__ deg) {
    int t = threadIdx.x, lane = t & 31, w = t >> 5;
    int idx = blockIdx.x * 256 + t;
    int c = (idx < NN) ? cnt[idx] : 0;
    int inc = c;
#pragma unroll
    for (int o = 1; o < 32; o <<= 1) {
        int u = __shfl_up_sync(0xFFFFFFFFu, inc, o);
        if (lane >= o) inc += u;
    }
    __shared__ int ws[8];
    if (lane == 31) ws[w] = inc;
    __syncthreads();
    int add = boff[blockIdx.x];
    for (int i = 0; i < w; ++i) add += ws[i];
    int exc = inc - c + add;
    if (idx < NN) {
        rowptr[idx] = exc;
        pos[idx] = exc;
        deg[idx] = (float)c;
    }
}

__global__ void fill_kernel(const void* __restrict__ edges, const int* __restrict__ is64p,
                            int* __restrict__ pos, int* __restrict__ esrc) {
    int e = blockIdx.x * blockDim.x + threadIdx.x;
    if (e >= EE) return;
    int is64 = *is64p;
    int s = idx_at(edges, is64, (size_t)e);
    int d = idx_at(edges, is64, (size_t)EE + e);
    if (d < 0 || d >= NN) return;
    if (s < 0) s = 0; if (s >= NN) s = NN - 1;
    int slot = atomicAdd(&pos[d], 1);
    if (slot >= 0 && slot < EE) esrc[slot] = s;
}

// ---------------- weight composition ----------------
__global__ void compose_kernel(const float* __restrict__ Wm, const float* __restrict__ Wu,
                               float* __restrict__ Wc) {
    int i = blockIdx.x >> 7;
    int k4 = (blockIdx.x & 127) * 4;
    int c = threadIdx.x;
    __shared__ float row[4][256];
#pragma unroll
    for (int q = 0; q < 4; ++q)
        row[q][c] = Wm[((size_t)i * 512 + k4 + q) * 256 + c];
    __syncthreads();
    const float* wub = Wu + ((size_t)i * 512 + 256) * 256;
    float acc0 = 0.f, acc1 = 0.f, acc2 = 0.f, acc3 = 0.f;
#pragma unroll 8
    for (int j = 0; j < 256; ++j) {
        float wv = wub[(size_t)j * 256 + c];
        acc0 += row[0][j] * wv;
        acc1 += row[1][j] * wv;
        acc2 += row[2][j] * wv;
        acc3 += row[3][j] * wv;
    }
    Wc[((size_t)i * 512 + k4 + 0) * 256 + c] = acc0;
    Wc[((size_t)i * 512 + k4 + 1) * 256 + c] = acc1;
    Wc[((size_t)i * 512 + k4 + 2) * 256 + c] = acc2;
    Wc[((size_t)i * 512 + k4 + 3) * 256 + c] = acc3;
}

__global__ void compose_bias_kernel(const float* __restrict__ b_msg,
                                    const float* __restrict__ Wu,
                                    float* __restrict__ bc) {
    int i = blockIdx.x;
    int c = threadIdx.x;
    __shared__ float bm[256];
    bm[c] = b_msg[(size_t)i * 256 + c];
    __syncthreads();
    const float* wub = Wu + ((size_t)i * 512 + 256) * 256;
    float acc = 0.f;
#pragma unroll 8
    for (int j = 0; j < 256; ++j)
        acc += bm[j] * wub[(size_t)j * 256 + c];
    bc[(size_t)i * 256 + c] = acc;
}

// ---------------- B split+transpose, hi/lo interleaved ----------------
__global__ void bsplit_kernel(const float* __restrict__ Wu, const float* __restrict__ Wc,
                              uint32_t* __restrict__ Bti) {
    int hop = blockIdx.x >> 8;
    int n = blockIdx.x & 255;
    const float* wu = Wu + (size_t)hop * 512 * 256;
    const float* wc = Wc + (size_t)hop * 512 * 256;
    size_t base = ((size_t)hop * 256 + n) * 768;
    for (int w = threadIdx.x; w < 384; w += 128) {
        int k = 2 * w;
        float f0 = (k < 256) ? wu[(size_t)k * 256 + n] : wc[(size_t)(k - 256) * 256 + n];
        float f1 = (k + 1 < 256) ? wu[(size_t)(k + 1) * 256 + n]
                                 : wc[(size_t)(k + 1 - 256) * 256 + n];
        uint32_t hi, lo;
        split_pair(f0, f1, hi, lo);
        Bti[base + 2 * w]     = hi;
        Bti[base + 2 * w + 1] = lo;
    }
}

// ---------------- initial node states (8 nodes/block, W_proj in smem) ----------------
__global__ __launch_bounds__(256)
void init_kernel(const float* __restrict__ nodes,
                 const void* __restrict__ types, const int* __restrict__ is64p,
                 const float* __restrict__ type_emb,
                 const float* __restrict__ W_proj,
                 const float* __restrict__ b_proj,
                 float* __restrict__ h) {
    __shared__ float Wp[FEAT * DD];
    __shared__ float sn[8][FEAT];
    int j = threadIdx.x;
    int v0 = blockIdx.x * 8;
    for (int i = j; i < FEAT * DD; i += 256)
        Wp[i] = W_proj[i];
    {
        int vv = v0 + (j >> 5);
        int kk = j & 31;
        sn[j >> 5][kk] = (vv < NN) ? nodes[(size_t)vv * FEAT + kk] : 0.f;
    }
    __syncthreads();
    float bp = b_proj[j];
    int is64 = *is64p;
#pragma unroll 1
    for (int q = 0; q < 8; ++q) {
        int v = v0 + q;
        if (v >= NN) break;
        int t = idx_at(types, is64, (size_t)v);
        if (t < 0) t = 0; if (t > 9) t = 9;
        float acc = bp + type_emb[(size_t)t * DD + j];
#pragma unroll 8
        for (int k = 0; k < FEAT; ++k)
            acc += sn[q][k] * Wp[k * DD + j];
        h[(size_t)v * DD + j] = acc;
    }
}

// ---------------- per-dst gather (float4-vectorized, 4 nodes/block) ----------------
__global__ __launch_bounds__(256)
void agg_gather_kernel(const int* __restrict__ rowptr,
                       const int* __restrict__ esrc,
                       const float* __restrict__ h,
                       float* __restrict__ S) {
    int v = blockIdx.x * 4 + (threadIdx.x >> 6);
    int tx = (threadIdx.x & 63) * 4;
    if (v >= NN) return;
    int beg = rowptr[v];
    int end = rowptr[v + 1];
    float4 acc = make_float4(0.f, 0.f, 0.f, 0.f);
    int i = beg;
    for (; i + 4 <= end; i += 4) {
        int s0 = esrc[i + 0];
        int s1 = esrc[i + 1];
        int s2 = esrc[i + 2];
        int s3 = esrc[i + 3];
        float4 a0 = *reinterpret_cast<const float4*>(h + (size_t)s0 * DD + tx);
        float4 a1 = *reinterpret_cast<const float4*>(h + (size_t)s1 * DD + tx);
        float4 a2 = *reinterpret_cast<const float4*>(h + (size_t)s2 * DD + tx);
        float4 a3 = *reinterpret_cast<const float4*>(h + (size_t)s3 * DD + tx);
        acc.x += (a0.x + a1.x) + (a2.x + a3.x);
        acc.y += (a0.y + a1.y) + (a2.y + a3.y);
        acc.z += (a0.z + a1.z) + (a2.z + a3.z);
        acc.w += (a0.w + a1.w) + (a2.w + a3.w);
    }
    for (; i < end; ++i) {
        float4 a = *reinterpret_cast<const float4*>(h + (size_t)esrc[i] * DD + tx);
        acc.x += a.x; acc.y += a.y; acc.z += a.z; acc.w += a.w;
    }
    *reinterpret_cast<float4*>(S + (size_t)v * DD + tx) = acc;
}

// ---------------- hybrid fused hop GEMM (round-13 proven, 75% H) ----------------
// h'[r][c] = relu( h@Wu_top + S@Wc1 + deg*(h@Wc2) + b_upd + deg*bc )
// H path (3/4 CTAs): bf16 m16n8k16 HMMA, hi/lo interleaved smem, LDS.64 frags.
#define SMU_BYTES 40960

__global__ __launch_bounds__(256, 2)
void hybrid_gemm_kernel(const float* __restrict__ h, const float* __restrict__ S,
                        const uint32_t* __restrict__ Bti,
                        const float* __restrict__ Wu, const float* __restrict__ Wc,
                        const float* __restrict__ b_upd_i, const float* __restrict__ bc_i,
                        const float* __restrict__ deg,
                        float* __restrict__ out) {
    __shared__ __align__(16) uint8_t smu[SMU_BYTES];
    int tid = threadIdx.x;
    int rowBase = blockIdx.y * 128;
    int colBase = blockIdx.x * 128;
    int lin = blockIdx.y * 2 + blockIdx.x;
    bool useH = (lin % 4) < 3;     // 75% tensor path

    const float* Xs[3] = { h, S, h };

    if (useH) {
        uint32_t* AW = (uint32_t*)(smu);           // [128][40] words interleaved
        uint32_t* BW = (uint32_t*)(smu + 20480);   // [128][40] words interleaved

        int wid = tid >> 5, lane = tid & 31;
        int tq = lane >> 2, tr = lane & 3;
        int warp_m = wid & 1, warp_n = wid >> 1;

        float acc[4][4][4];
#pragma unroll
        for (int mt = 0; mt < 4; ++mt)
#pragma unroll
            for (int nt = 0; nt < 4; ++nt)
#pragma unroll
                for (int q = 0; q < 4; ++q) acc[mt][nt][q] = 0.0f;

        int arow = tid >> 1;
        int halfsel = tid & 1;
        int gr = rowBase + arow;
        bool ok = gr < NN;
        float rs = ok ? deg[gr] : 0.f;

        const uint32_t* Bn = Bti + (size_t)(colBase + arow) * 768;
        uint32_t* aw = AW + arow * 40 + halfsel * 16;
        uint32_t* bw = BW + arow * 40 + halfsel * 16;

#pragma unroll 1
        for (int p = 0; p < 3; ++p) {
            const float* X = Xs[p];
            bool scaled = (p == 2);
#pragma unroll 1
            for (int kt = 0; kt < 8; ++kt) {
                int k0 = kt * 32;
                __syncthreads();
                // --- A tile: load 16 floats, split, store interleaved (4x STS.128) ---
                {
                    float4 v[4];
                    if (ok) {
                        const float4* src = reinterpret_cast<const float4*>(
                            X + (size_t)gr * DD + k0 + halfsel * 16);
#pragma unroll
                        for (int i = 0; i < 4; ++i) v[i] = src[i];
                        if (scaled) {
#pragma unroll
                            for (int i = 0; i < 4; ++i) {
                                v[i].x *= rs; v[i].y *= rs; v[i].z *= rs; v[i].w *= rs;
                            }
                        }
                    } else {
#pragma unroll
                        for (int i = 0; i < 4; ++i) v[i] = make_float4(0.f, 0.f, 0.f, 0.f);
                    }
#pragma unroll
                    for (int i = 0; i < 4; ++i) {
                        uint4 pk;
                        split_pair(v[i].x, v[i].y, pk.x, pk.y);
                        split_pair(v[i].z, v[i].w, pk.z, pk.w);
                        *reinterpret_cast<uint4*>(aw + 4 * i) = pk;
                    }
                }
                // --- B tile: straight uint4 copy of pre-interleaved words ---
                {
                    int bw0 = (p * 8 + kt) * 32 + halfsel * 16;
#pragma unroll
                    for (int i = 0; i < 4; ++i)
                        *reinterpret_cast<uint4*>(bw + 4 * i) =
                            *reinterpret_cast<const uint4*>(Bn + bw0 + 4 * i);
                }
                __syncthreads();
                // --- compute: 2 k16 steps, LDS.64 fragment loads ---
#pragma unroll
                for (int ks = 0; ks < 2; ++ks) {
                    int kw2 = ks * 16 + tr * 2;
                    uint32_t ah[4][4], al[4][4], bh[4][2], bl[4][2];
#pragma unroll
                    for (int mt = 0; mt < 4; ++mt) {
                        int base = (warp_m * 64 + mt * 16 + tq) * 40 + kw2;
                        uint2 q0 = *reinterpret_cast<const uint2*>(AW + base);
                        uint2 q1 = *reinterpret_cast<const uint2*>(AW + base + 8 * 40);
                        uint2 q2 = *reinterpret_cast<const uint2*>(AW + base + 8);
                        uint2 q3 = *reinterpret_cast<const uint2*>(AW + base + 8 * 40 + 8);
                        ah[mt][0] = q0.x; al[mt][0] = q0.y;
                        ah[mt][1] = q1.x; al[mt][1] = q1.y;
                        ah[mt][2] = q2.x; al[mt][2] = q2.y;
                        ah[mt][3] = q3.x; al[mt][3] = q3.y;
                    }
#pragma unroll
                    for (int nt = 0; nt < 4; ++nt) {
                        int base = (warp_n * 32 + nt * 8 + tq) * 40 + kw2;
                        uint2 r0 = *reinterpret_cast<const uint2*>(BW + base);
                        uint2 r1 = *reinterpret_cast<const uint2*>(BW + base + 8);
                        bh[nt][0] = r0.x; bl[nt][0] = r0.y;
                        bh[nt][1] = r1.x; bl[nt][1] = r1.y;
                    }
#pragma unroll
                    for (int mt = 0; mt < 4; ++mt)
#pragma unroll
                        for (int nt = 0; nt < 4; ++nt) {
                            mma_bf16(acc[mt][nt], ah[mt], bl[nt]);
                            mma_bf16(acc[mt][nt], al[mt], bh[nt]);
                            mma_bf16(acc[mt][nt], ah[mt], bh[nt]);
                        }
                }
            }
        }
        // epilogue
#pragma unroll
        for (int mt = 0; mt < 4; ++mt) {
            int r0 = rowBase + warp_m * 64 + mt * 16 + tq;
            int r1 = r0 + 8;
            float d0 = (r0 < NN) ? deg[r0] : 0.f;
            float d1 = (r1 < NN) ? deg[r1] : 0.f;
#pragma unroll
            for (int nt = 0; nt < 4; ++nt) {
                int c = colBase + warp_n * 32 + nt * 8 + tr * 2;
                float bu0 = b_upd_i[c], bu1 = b_upd_i[c + 1];
                float bb0 = bc_i[c],   bb1 = bc_i[c + 1];
                if (r0 < NN) {
                    float2 v;
                    v.x = fmaxf(acc[mt][nt][0] + bu0 + d0 * bb0, 0.f);
                    v.y = fmaxf(acc[mt][nt][1] + bu1 + d0 * bb1, 0.f);
                    *reinterpret_cast<float2*>(out + (size_t)r0 * DD + c) = v;
                }
                if (r1 < NN) {
                    float2 v;
                    v.x = fmaxf(acc[mt][nt][2] + bu0 + d1 * bb0, 0.f);
                    v.y = fmaxf(acc[mt][nt][3] + bu1 + d1 * bb1, 0.f);
                    *reinterpret_cast<float2*>(out + (size_t)r1 * DD + c) = v;
                }
            }
        }
    } else {
        // ======== fp32 FFMA path (BKK=16) ========
        float* Af = (float*)smu;            // [16][128]
        float* Bf = (float*)(smu + 8192);   // [16][128]
        int tx = tid & 15, ty = tid >> 4;

        const float* Bp[3] = { Wu, Wc, Wc + 65536 };

        float acc[8][8];
#pragma unroll
        for (int i = 0; i < 8; ++i)
#pragma unroll
            for (int j = 0; j < 8; ++j) acc[i][j] = 0.0f;

        int la_row = tid >> 1, la_k = (tid & 1) * 8;
        int lb_k = tid >> 4, lb_col = (tid & 15) * 8;
        int gr = rowBase + la_row;
        bool ok = gr < NN;
        float rs = ok ? deg[gr] : 0.f;

#pragma unroll 1
        for (int p = 0; p < 3; ++p) {
            const float* X = Xs[p];
            const float* B = Bp[p];
            bool scaled = (p == 2);
#pragma unroll 1
            for (int k0 = 0; k0 < DD; k0 += 16) {
                float4 av0 = make_float4(0.f, 0.f, 0.f, 0.f), av1 = av0;
                if (ok) {
                    const float4* src = reinterpret_cast<const float4*>(
                        X + (size_t)gr * DD + k0 + la_k);
                    av0 = src[0]; av1 = src[1];
                    if (scaled) {
                        av0.x *= rs; av0.y *= rs; av0.z *= rs; av0.w *= rs;
                        av1.x *= rs; av1.y *= rs; av1.z *= rs; av1.w *= rs;
                    }
                }
                const float4* bsrc = reinterpret_cast<const float4*>(
                    B + (size_t)(k0 + lb_k) * DD + colBase + lb_col);
                float4 bv0 = bsrc[0], bv1 = bsrc[1];
                Af[(la_k + 0) * 128 + la_row] = av0.x;
                Af[(la_k + 1) * 128 + la_row] = av0.y;
                Af[(la_k + 2) * 128 + la_row] = av0.z;
                Af[(la_k + 3) * 128 + la_row] = av0.w;
                Af[(la_k + 4) * 128 + la_row] = av1.x;
                Af[(la_k + 5) * 128 + la_row] = av1.y;
                Af[(la_k + 6) * 128 + la_row] = av1.z;
                Af[(la_k + 7) * 128 + la_row] = av1.w;
                *reinterpret_cast<float4*>(&Bf[lb_k * 128 + lb_col]) = bv0;
                *reinterpret_cast<float4*>(&Bf[lb_k * 128 + lb_col + 4]) = bv1;
                __syncthreads();
#pragma unroll
                for (int k = 0; k < 16; ++k) {
                    float a[8], b[8];
                    *reinterpret_cast<float4*>(&a[0]) =
                        *reinterpret_cast<const float4*>(&Af[k * 128 + ty * 4]);
                    *reinterpret_cast<float4*>(&a[4]) =
                        *reinterpret_cast<const float4*>(&Af[k * 128 + 64 + ty * 4]);
                    *reinterpret_cast<float4*>(&b[0]) =
                        *reinterpret_cast<const float4*>(&Bf[k * 128 + tx * 4]);
                    *reinterpret_cast<float4*>(&b[4]) =
                        *reinterpret_cast<const float4*>(&Bf[k * 128 + 64 + tx * 4]);
#pragma unroll
                    for (int i = 0; i < 8; ++i)
#pragma unroll
                        for (int j = 0; j < 8; ++j)
                            acc[i][j] += a[i] * b[j];
                }
                __syncthreads();
            }
        }
#pragma unroll
        for (int i = 0; i < 8; ++i) {
            int rloc = (i < 4) ? (ty * 4 + i) : (64 + ty * 4 + i - 4);
            int r = rowBase + rloc;
            if (r >= NN) continue;
            float dr = deg[r];
#pragma unroll
            for (int g = 0; g < 2; ++g) {
                int c0 = colBase + g * 64 + tx * 4;
                float4 v;
                float* vp = &v.x;
#pragma unroll
                for (int j = 0; j < 4; ++j) {
                    int jj = g * 4 + j;
                    vp[j] = fmaxf(acc[i][jj] + b_upd_i[c0 + j] + dr * bc_i[c0 + j], 0.f);
                }
                *reinterpret_cast<float4*>(out + (size_t)r * DD + c0) = v;
            }
        }
    }
}

// ---------------- max pool over nodes ----------------
__global__ void pool_kernel(const float* __restrict__ h, float* __restrict__ pool) {
    int j = threadIdx.x;
    int r0 = blockIdx.x * 256;
    int r1 = min(r0 + 256, NN);
    float m = 0.0f;
    for (int r = r0; r < r1; ++r)
        m = fmaxf(m, h[(size_t)r * DD + j]);
    atomicMax(reinterpret_cast<int*>(&pool[j]), __float_as_int(m));
}

// ---------------- final projection ----------------
__global__ void out_kernel(const float* __restrict__ pool,
                           const float* __restrict__ W_out,
                           const float* __restrict__ b_out,
                           float* __restrict__ out) {
    __shared__ float sp[DD];
    int j = threadIdx.x;
    sp[j] = pool[j];
    __syncthreads();
    float acc = b_out[j];
#pragma unroll 8
    for (int k = 0; k < DD; ++k)
        acc += sp[k] * W_out[(size_t)k * DD + j];
    out[j] = acc;
}

// ---------------- launch ----------------
extern "C" void kernel_launch(void* const* d_in, const int* in_sizes, int n_in,
                              void* d_out, int out_size) {
    const float* nodes      = (const float*)d_in[0];
    const void*  edges      = d_in[1];
    const void*  node_types = d_in[2];
    const float* type_emb   = (const float*)d_in[3];
    const float* W_proj     = (const float*)d_in[4];
    const float* b_proj     = (const float*)d_in[5];
    const float* W_msg      = (const float*)d_in[6];
    const float* b_msg      = (const float*)d_in[7];
    const float* W_upd      = (const float*)d_in[8];
    const float* b_upd      = (const float*)d_in[9];
    const float* W_out      = (const float*)d_in[10];
    const float* b_out      = (const float*)d_in[11];
    float* out = (float*)d_out;

    float *h_p, *h2_p, *S_p, *Wc_p, *bc_p, *deg_p, *pool_p;
    uint32_t *Bti_p;
    int *cnt_p, *rowptr_p, *pos_p, *esrc_p, *is64_p, *bsum_p, *boff_p;
    cudaGetSymbolAddress((void**)&h_p,      g_h);
    cudaGetSymbolAddress((void**)&h2_p,     g_h2);
    cudaGetSymbolAddress((void**)&S_p,      g_S);
    cudaGetSymbolAddress((void**)&Wc_p,     g_Wc);
    cudaGetSymbolAddress((void**)&bc_p,     g_bc);
    cudaGetSymbolAddress((void**)&Bti_p,    g_Bti);
    cudaGetSymbolAddress((void**)&deg_p,    g_deg);
    cudaGetSymbolAddress((void**)&pool_p,   g_pool);
    cudaGetSymbolAddress((void**)&cnt_p,    g_cnt);
    cudaGetSymbolAddress((void**)&rowptr_p, g_rowptr);
    cudaGetSymbolAddress((void**)&pos_p,    g_pos);
    cudaGetSymbolAddress((void**)&esrc_p,   g_esrc);
    cudaGetSymbolAddress((void**)&is64_p,   g_is64);
    cudaGetSymbolAddress((void**)&bsum_p,   g_bsum);
    cudaGetSymbolAddress((void**)&boff_p,   g_boff);

    // sniff index dtype
    detect_kernel<<<1, 256>>>((const int*)edges, is64_p);

    // CSR build (parallel scan)
    zero_i_kernel<<<(NN + 255) / 256, 256>>>(cnt_p, NN);
    count_kernel<<<(EE + 255) / 256, 256>>>(edges, is64_p, cnt_p);
    csr_sum_kernel<<<NB, 256>>>(cnt_p, bsum_p);
    csr_scanb_kernel<<<1, 128>>>(bsum_p, boff_p, rowptr_p);
    csr_apply_kernel<<<NB, 256>>>(cnt_p, boff_p, rowptr_p, pos_p, deg_p);
    fill_kernel<<<(EE + 255) / 256, 256>>>(edges, is64_p, pos_p, esrc_p);

    // composed weights + bias + interleaved split B
    compose_kernel<<<HOPS * 128, 256>>>(W_msg, W_upd, Wc_p);
    compose_bias_kernel<<<HOPS, 256>>>(b_msg, W_upd, bc_p);
    bsplit_kernel<<<HOPS * 256, 128>>>(W_upd, Wc_p, Bti_p);

    // initial states
    init_kernel<<<(NN + 7) / 8, 256>>>(nodes, node_types, is64_p, type_emb,
                                       W_proj, b_proj, h_p);

    float* h_cur = h_p;
    float* h_nxt = h2_p;
    dim3 ggrid(2, (NN + 127) / 128);

    for (int i = 0; i < HOPS; ++i) {
        agg_gather_kernel<<<(NN + 3) / 4, 256>>>(rowptr_p, esrc_p, h_cur, S_p);
        hybrid_gemm_kernel<<<ggrid, 256>>>(
            h_cur, S_p,
            Bti_p + (size_t)i * 256 * 768,
            W_upd + (size_t)i * 512 * 256, Wc_p + (size_t)i * 512 * 256,
            b_upd + (size_t)i * DD, bc_p + (size_t)i * DD,
            deg_p, h_nxt);
        float* t = h_cur; h_cur = h_nxt; h_nxt = t;
    }

    // pool + output
    zero_f_kernel<<<1, DD>>>(pool_p, DD);
    pool_kernel<<<(NN + 255) / 256, DD>>>(h_cur, pool_p);
    out_kernel<<<1, DD>>>(pool_p, W_out, b_out, out);
}